// round 2
// baseline (speedup 1.0000x reference)
#include <cuda_runtime.h>
#include <math.h>

#define B_ 64
#define NV_ 21
#define BN_ 1344
#define L_ 2048
#define PATCH_ 16
#define PNUM_ 255
#define D_ 128
#define H_ 256
#define PRED_ 96
#define ROWS_ (BN_*PNUM_)      /* 342720 */
#define KHEAD_ (D_*PNUM_)      /* 32640  */
#define EPS_ 1e-5f
#define EMASCALE_ 0.7071067811865476f

// ---- scratch (no cudaMalloc allowed) ----
__device__ float g_bufA[ROWS_*D_];
__device__ float g_bufB[ROWS_*D_];
__device__ float g_u[BN_*KHEAD_];
__device__ float g_ema[D_*4];

__device__ __forceinline__ float2 ffma2(float2 a, float2 b, float2 c) {
    unsigned long long au = *reinterpret_cast<unsigned long long*>(&a);
    unsigned long long bu = *reinterpret_cast<unsigned long long*>(&b);
    unsigned long long cu = *reinterpret_cast<unsigned long long*>(&c);
    unsigned long long ru;
    asm("fma.rn.f32x2 %0, %1, %2, %3;" : "=l"(ru) : "l"(au), "l"(bu), "l"(cu));
    return *reinterpret_cast<float2*>(&ru);
}

// =====================================================================
// K0: EMA params -> per-(d,n) recurrence coefficients q, a
// =====================================================================
__global__ void k0_emaparam(const float* __restrict__ delta, const float* __restrict__ alpha,
                            const float* __restrict__ beta, const float* __restrict__ gamma)
{
    int d = threadIdx.x;
    if (d < D_) {
        #pragma unroll
        for (int n = 0; n < 2; n++) {
            int i = d*2 + n;
            float p = 1.f/(1.f + expf(-delta[i]));
            float q = 1.f - p * (1.f/(1.f + expf(-alpha[i])));
            float a = p * beta[i] * gamma[i] * EMASCALE_;
            g_ema[d*4 + n*2 + 0] = q;
            g_ema[d*4 + n*2 + 1] = a;
        }
    }
}

// =====================================================================
// K1: patch gather + feature-projection LEMblock (16->256->128 + res + LN)
// smem: h2[256][17] f2, p2[16][17] f2, w2s[256*128], ys[32][130], gs/bes
// =====================================================================
#define SM1_BYTES ((256*17 + 16*17)*8 + (256*128 + 32*130 + 256)*4)

__global__ __launch_bounds__(256, 1)
void k1_featproj(const float* __restrict__ x,
                 const float* __restrict__ w1, const float* __restrict__ b1,
                 const float* __restrict__ w2, const float* __restrict__ b2,
                 const float* __restrict__ wr, const float* __restrict__ br,
                 const float* __restrict__ g,  const float* __restrict__ be)
{
    extern __shared__ unsigned char smraw[];
    float2* h2 = (float2*)smraw;               // [256][17]
    float2* p2 = h2 + 256*17;                  // [16][17]
    float*  w2s = (float*)(p2 + 16*17);        // [256*128]
    float*  ys  = w2s + 256*128;               // [32][130]
    float*  gs  = ys + 32*130;                 // [128]
    float*  bes = gs + 128;                    // [128]

    int tid = threadIdx.x;
    for (int i = tid; i < 256*128; i += 256) w2s[i] = w2[i];
    if (tid < 128) { gs[tid] = g[tid]; bes[tid] = be[tid]; }

    float w1r[16];
    #pragma unroll
    for (int k = 0; k < 16; k++) w1r[k] = w1[k*256 + tid];
    float b1r = b1[tid];

    int cB = tid & 127, rg = tid >> 7;
    float wrr[16];
    #pragma unroll
    for (int k = 0; k < 16; k++) wrr[k] = wr[k*128 + cB];
    float bB = b2[cB] + br[cB];

    const int NTILES = ROWS_/32;   // 10710
    for (int tile = blockIdx.x; tile < NTILES; tile += gridDim.x) {
        int row0 = tile*32;
        __syncthreads();                                   // (1) protect reuse
        for (int i = tid; i < 32*16; i += 256) {
            int r = i >> 4, k = i & 15;
            int grow = row0 + r;
            int bn = grow / 255, p = grow - bn*255;
            float v = x[bn*L_ + p*8 + k];
            ((float*)(p2 + k*17 + (r>>1)))[r & 1] = v;
        }
        __syncthreads();                                   // (2)

        // phase A: h = relu(patch @ w1 + b1), col = tid, 32 rows packed
        float2 hacc[16];
        #pragma unroll
        for (int rp = 0; rp < 16; rp++) hacc[rp] = make_float2(b1r, b1r);
        #pragma unroll
        for (int k = 0; k < 16; k++) {
            float2 wv = make_float2(w1r[k], w1r[k]);
            #pragma unroll
            for (int rp = 0; rp < 16; rp++)
                hacc[rp] = ffma2(p2[k*17 + rp], wv, hacc[rp]);
        }
        #pragma unroll
        for (int rp = 0; rp < 16; rp++) {
            hacc[rp].x = fmaxf(hacc[rp].x, 0.f);
            hacc[rp].y = fmaxf(hacc[rp].y, 0.f);
        }

        // residual: patch @ wr + (b2+br), col = cB, 16 rows (this rg)
        float2 acc[8];
        #pragma unroll
        for (int j = 0; j < 8; j++) acc[j] = make_float2(bB, bB);
        #pragma unroll
        for (int k = 0; k < 16; k++) {
            float2 wv = make_float2(wrr[k], wrr[k]);
            #pragma unroll
            for (int j = 0; j < 8; j++)
                acc[j] = ffma2(p2[k*17 + rg*8 + j], wv, acc[j]);
        }
        __syncthreads();                                   // (3) prev h2 reads done
        #pragma unroll
        for (int rp = 0; rp < 16; rp++) h2[tid*17 + rp] = hacc[rp];
        __syncthreads();                                   // (4)

        // phase B: y += h @ w2
        #pragma unroll 2
        for (int k = 0; k < 256; k++) {
            float wv = w2s[k*128 + cB];
            float2 wv2 = make_float2(wv, wv);
            #pragma unroll
            for (int j = 0; j < 8; j++)
                acc[j] = ffma2(h2[k*17 + rg*8 + j], wv2, acc[j]);
        }
        #pragma unroll
        for (int j = 0; j < 8; j++) {
            ys[(rg*16 + 2*j  )*130 + cB] = acc[j].x;
            ys[(rg*16 + 2*j+1)*130 + cB] = acc[j].y;
        }
        __syncthreads();                                   // (5)

        // LayerNorm: 8 threads per row
        {
            int r = tid >> 3, seg = tid & 7;
            float s = 0.f, q = 0.f;
            #pragma unroll
            for (int i = 0; i < 16; i++) {
                float v = ys[r*130 + seg*16 + i];
                s += v; q += v*v;
            }
            #pragma unroll
            for (int m = 1; m < 8; m <<= 1) {
                s += __shfl_xor_sync(0xffffffffu, s, m);
                q += __shfl_xor_sync(0xffffffffu, q, m);
            }
            float mu = s * (1.f/128.f);
            float rstd = rsqrtf(q*(1.f/128.f) - mu*mu + EPS_);
            float* outp = g_bufA + (size_t)(row0 + r)*D_ + seg*16;
            #pragma unroll
            for (int i = 0; i < 16; i += 4) {
                float4 o;
                int c = seg*16 + i;
                o.x = (ys[r*130+c+0]-mu)*rstd*gs[c+0] + bes[c+0];
                o.y = (ys[r*130+c+1]-mu)*rstd*gs[c+1] + bes[c+1];
                o.z = (ys[r*130+c+2]-mu)*rstd*gs[c+2] + bes[c+2];
                o.w = (ys[r*130+c+3]-mu)*rstd*gs[c+3] + bes[c+3];
                *(float4*)(outp + i) = o;
            }
        }
    }
}

// =====================================================================
// K2: encoder LEMblock (128->128->128 + res + LN), runs twice
// smem: xh2[128][17] f2 (x then h), w1s/w2s/wrs 64KB each, ys, gs/bes
// =====================================================================
#define SM2_BYTES ((128*17)*8 + (3*128*128 + 32*130 + 256)*4)

__global__ __launch_bounds__(256, 1)
void k2_encoder(const float* __restrict__ ew1, const float* __restrict__ eb1,
                const float* __restrict__ ew2, const float* __restrict__ eb2,
                const float* __restrict__ ewr, const float* __restrict__ ebr,
                const float* __restrict__ eg,  const float* __restrict__ ebe,
                int layer)
{
    extern __shared__ unsigned char smraw[];
    float2* xh2 = (float2*)smraw;              // [128][17]
    float* w1s = (float*)(xh2 + 128*17);
    float* w2s = w1s + 128*128;
    float* wrs = w2s + 128*128;
    float* ys  = wrs + 128*128;                // [32][130]
    float* gs  = ys + 32*130;
    float* bes = gs + 128;

    const float* w1 = ew1 + layer*D_*D_;
    const float* w2 = ew2 + layer*D_*D_;
    const float* wr = ewr + layer*D_*D_;
    const float* zin  = layer ? g_bufB : g_bufA;
    float*       zout = layer ? g_bufA : g_bufB;

    int tid = threadIdx.x;
    for (int i = tid; i < 128*128; i += 256) {
        w1s[i] = w1[i]; w2s[i] = w2[i]; wrs[i] = wr[i];
    }
    if (tid < 128) { gs[tid] = eg[layer*128 + tid]; bes[tid] = ebe[layer*128 + tid]; }
    int cB = tid & 127, rg = tid >> 7;
    float b1r = eb1[layer*128 + cB];
    float bB  = eb2[layer*128 + cB] + ebr[layer*128 + cB];

    const int NTILES = ROWS_/32;
    for (int tile = blockIdx.x; tile < NTILES; tile += gridDim.x) {
        size_t row0 = (size_t)tile*32;
        __syncthreads();                                   // (1)
        for (int i = tid; i < 32*128; i += 256) {
            int r = i >> 7, c = i & 127;
            ((float*)(xh2 + c*17 + (r>>1)))[r & 1] = zin[(row0 + r)*D_ + c];
        }
        __syncthreads();                                   // (2)

        // residual and hidden together (share x loads)
        float2 racc[8], hacc[8];
        #pragma unroll
        for (int j = 0; j < 8; j++) { racc[j] = make_float2(bB, bB); hacc[j] = make_float2(b1r, b1r); }
        #pragma unroll 2
        for (int k = 0; k < 128; k++) {
            float wrv = wrs[k*128 + cB];
            float w1v = w1s[k*128 + cB];
            float2 wr2 = make_float2(wrv, wrv);
            float2 w12 = make_float2(w1v, w1v);
            #pragma unroll
            for (int j = 0; j < 8; j++) {
                float2 xv = xh2[k*17 + rg*8 + j];
                racc[j] = ffma2(xv, wr2, racc[j]);
                hacc[j] = ffma2(xv, w12, hacc[j]);
            }
        }
        #pragma unroll
        for (int j = 0; j < 8; j++) {
            hacc[j].x = fmaxf(hacc[j].x, 0.f);
            hacc[j].y = fmaxf(hacc[j].y, 0.f);
        }
        __syncthreads();                                   // (3) everyone done reading x
        #pragma unroll
        for (int j = 0; j < 8; j++) xh2[cB*17 + rg*8 + j] = hacc[j];
        __syncthreads();                                   // (4)

        // phase B: y = racc + h @ w2
        #pragma unroll 2
        for (int k = 0; k < 128; k++) {
            float wv = w2s[k*128 + cB];
            float2 wv2 = make_float2(wv, wv);
            #pragma unroll
            for (int j = 0; j < 8; j++)
                racc[j] = ffma2(xh2[k*17 + rg*8 + j], wv2, racc[j]);
        }
        #pragma unroll
        for (int j = 0; j < 8; j++) {
            ys[(rg*16 + 2*j  )*130 + cB] = racc[j].x;
            ys[(rg*16 + 2*j+1)*130 + cB] = racc[j].y;
        }
        __syncthreads();                                   // (5)

        {
            int r = tid >> 3, seg = tid & 7;
            float s = 0.f, q = 0.f;
            #pragma unroll
            for (int i = 0; i < 16; i++) {
                float v = ys[r*130 + seg*16 + i];
                s += v; q += v*v;
            }
            #pragma unroll
            for (int m = 1; m < 8; m <<= 1) {
                s += __shfl_xor_sync(0xffffffffu, s, m);
                q += __shfl_xor_sync(0xffffffffu, q, m);
            }
            float mu = s * (1.f/128.f);
            float rstd = rsqrtf(q*(1.f/128.f) - mu*mu + EPS_);
            float* outp = zout + (row0 + r)*D_ + seg*16;
            #pragma unroll
            for (int i = 0; i < 16; i += 4) {
                float4 o;
                int c = seg*16 + i;
                o.x = (ys[r*130+c+0]-mu)*rstd*gs[c+0] + bes[c+0];
                o.y = (ys[r*130+c+1]-mu)*rstd*gs[c+1] + bes[c+1];
                o.z = (ys[r*130+c+2]-mu)*rstd*gs[c+2] + bes[c+2];
                o.w = (ys[r*130+c+3]-mu)*rstd*gs[c+3] + bes[c+3];
                *(float4*)(outp + i) = o;
            }
        }
    }
}

// =====================================================================
// K4: MultiHeadEMA as 2-state linear recurrence + residual + SiLU,
//     transposed write into head layout u[bn][d*255 + t]
// =====================================================================
__global__ void k4_ema(const float* __restrict__ omega)
{
    __shared__ float tile[128*65];
    int bn = blockIdx.x, d = threadIdx.x;
    float q0 = g_ema[d*4+0], a0 = g_ema[d*4+1];
    float q1 = g_ema[d*4+2], a1 = g_ema[d*4+3];
    float om = omega[d];
    const float* src = g_bufA + (size_t)bn*PNUM_*D_ + d;
    float* dst = g_u + (size_t)bn*KHEAD_;
    float s0 = 0.f, s1 = 0.f;
    for (int chunk = 0; chunk < 4; chunk++) {
        int tbase = chunk*64;
        int tn = (PNUM_ - tbase < 64) ? (PNUM_ - tbase) : 64;
        #pragma unroll 4
        for (int i = 0; i < tn; i++) {
            float xv = src[(size_t)(tbase + i)*D_];
            s0 = fmaf(s0, q0, xv);
            s1 = fmaf(s1, q1, xv);
            float v = fmaf(om, xv, fmaf(a0, s0, a1*s1));
            tile[d*65 + i] = v * (1.f/(1.f + __expf(-v)));
        }
        __syncthreads();
        for (int i = d; i < 128*64; i += 128) {
            int dd = i >> 6, tt = i & 63;
            if (tt < tn) dst[dd*PNUM_ + tbase + tt] = tile[dd*65 + tt];
        }
        __syncthreads();
    }
}

// =====================================================================
// K5: head GEMM [1344 x 32640] @ [32640 x 96], K-split=5 with atomics
// =====================================================================
__global__ void k5_init(const float* __restrict__ hb, float* __restrict__ out)
{
    int i = blockIdx.x*blockDim.x + threadIdx.x;
    if (i < BN_*PRED_) out[i] = hb[i % PRED_];
}

__global__ __launch_bounds__(192)
void k5_head(const float* __restrict__ hw, float* __restrict__ out)
{
    __shared__ float2 u2[64*17];
    __shared__ float ws[64*96];
    int tid = threadIdx.x;
    int cB = tid % 96, rg = tid / 96;
    int row0 = blockIdx.x * 32;
    float2 acc[8];
    #pragma unroll
    for (int j = 0; j < 8; j++) acc[j] = make_float2(0.f, 0.f);
    for (int ch = 0; ch < 102; ch++) {
        int k0 = (blockIdx.y * 102 + ch) * 64;
        __syncthreads();
        for (int i = tid; i < 32*64; i += 192) {
            int r = i >> 6, kk = i & 63;
            ((float*)(u2 + kk*17 + (r>>1)))[r & 1] = g_u[(size_t)(row0+r)*KHEAD_ + k0 + kk];
        }
        for (int i = tid; i < 64*96; i += 192) ws[i] = hw[(size_t)k0*96 + i];
        __syncthreads();
        #pragma unroll 2
        for (int kk = 0; kk < 64; kk++) {
            float wv = ws[kk*96 + cB];
            float2 wv2 = make_float2(wv, wv);
            #pragma unroll
            for (int j = 0; j < 8; j++)
                acc[j] = ffma2(u2[kk*17 + rg*8 + j], wv2, acc[j]);
        }
    }
    #pragma unroll
    for (int j = 0; j < 8; j++) {
        int r = row0 + rg*16 + 2*j;
        atomicAdd(&out[r*PRED_ + cB],     acc[j].x);
        atomicAdd(&out[(r+1)*PRED_ + cB], acc[j].y);
    }
}

// =====================================================================
extern "C" void kernel_launch(void* const* d_in, const int* in_sizes, int n_in,
                              void* d_out, int out_size)
{
    const float* x       = (const float*)d_in[0];
    const float* fp_w1   = (const float*)d_in[1];
    const float* fp_b1   = (const float*)d_in[2];
    const float* fp_w2   = (const float*)d_in[3];
    const float* fp_b2   = (const float*)d_in[4];
    const float* fp_wr   = (const float*)d_in[5];
    const float* fp_br   = (const float*)d_in[6];
    const float* fp_g    = (const float*)d_in[7];
    const float* fp_be   = (const float*)d_in[8];
    const float* enc_w1  = (const float*)d_in[9];
    const float* enc_b1  = (const float*)d_in[10];
    const float* enc_w2  = (const float*)d_in[11];
    const float* enc_b2  = (const float*)d_in[12];
    const float* enc_wr  = (const float*)d_in[13];
    const float* enc_br  = (const float*)d_in[14];
    const float* enc_g   = (const float*)d_in[15];
    const float* enc_be  = (const float*)d_in[16];
    const float* e_delta = (const float*)d_in[17];
    const float* e_alpha = (const float*)d_in[18];
    const float* e_beta  = (const float*)d_in[19];
    const float* e_gamma = (const float*)d_in[20];
    const float* e_omega = (const float*)d_in[21];
    const float* head_w  = (const float*)d_in[22];
    const float* head_b  = (const float*)d_in[23];
    float* out = (float*)d_out;

    cudaFuncSetAttribute(k1_featproj, cudaFuncAttributeMaxDynamicSharedMemorySize, SM1_BYTES);
    cudaFuncSetAttribute(k2_encoder,  cudaFuncAttributeMaxDynamicSharedMemorySize, SM2_BYTES);

    k0_emaparam<<<1, 128>>>(e_delta, e_alpha, e_beta, e_gamma);
    k1_featproj<<<148, 256, SM1_BYTES>>>(x, fp_w1, fp_b1, fp_w2, fp_b2, fp_wr, fp_br, fp_g, fp_be);
    k2_encoder<<<148, 256, SM2_BYTES>>>(enc_w1, enc_b1, enc_w2, enc_b2, enc_wr, enc_br, enc_g, enc_be, 0);
    k2_encoder<<<148, 256, SM2_BYTES>>>(enc_w1, enc_b1, enc_w2, enc_b2, enc_wr, enc_br, enc_g, enc_be, 1);
    k4_ema<<<BN_, 128>>>(e_omega);
    k5_init<<<(BN_*PRED_ + 255)/256, 256>>>(head_b, out);
    k5_head<<<dim3(42, 5), 192>>>(head_w, out);
}

// round 3
// speedup vs baseline: 1.0065x; 1.0065x over previous
#include <cuda_runtime.h>
#include <math.h>

#define B_ 64
#define NV_ 21
#define BN_ 1344
#define L_ 2048
#define PATCH_ 16
#define PNUM_ 255
#define D_ 128
#define H_ 256
#define PRED_ 96
#define ROWS_ (BN_*PNUM_)      /* 342720 */
#define KHEAD_ (D_*PNUM_)      /* 32640  */
#define EPS_ 1e-5f
#define EMASCALE_ 0.7071067811865476f

// ---- scratch (no cudaMalloc allowed) ----
__device__ float g_bufA[ROWS_*D_];
__device__ float g_bufB[ROWS_*D_];
__device__ float g_u[BN_*KHEAD_];
__device__ float g_ema[D_*4];

__device__ __forceinline__ float2 ffma2(float2 a, float2 b, float2 c) {
    unsigned long long au = *reinterpret_cast<unsigned long long*>(&a);
    unsigned long long bu = *reinterpret_cast<unsigned long long*>(&b);
    unsigned long long cu = *reinterpret_cast<unsigned long long*>(&c);
    unsigned long long ru;
    asm("fma.rn.f32x2 %0, %1, %2, %3;" : "=l"(ru) : "l"(au), "l"(bu), "l"(cu));
    return *reinterpret_cast<float2*>(&ru);
}

// =====================================================================
// K0: EMA params -> per-(d,n) recurrence coefficients q, a
// =====================================================================
__global__ void k0_emaparam(const float* __restrict__ delta, const float* __restrict__ alpha,
                            const float* __restrict__ beta, const float* __restrict__ gamma)
{
    int d = threadIdx.x;
    if (d < D_) {
        #pragma unroll
        for (int n = 0; n < 2; n++) {
            int i = d*2 + n;
            float p = 1.f/(1.f + expf(-delta[i]));
            float q = 1.f - p * (1.f/(1.f + expf(-alpha[i])));
            float a = p * beta[i] * gamma[i] * EMASCALE_;
            g_ema[d*4 + n*2 + 0] = q;
            g_ema[d*4 + n*2 + 1] = a;
        }
    }
}

// =====================================================================
// K1: patch gather + feature-projection LEMblock (16->256->128 + res + LN)
// smem: h2[256][17] f2, p2[16][17] f2, w2s[256*128], ys[32][130], gs/bes
// =====================================================================
#define SM1_BYTES ((256*17 + 16*17)*8 + (256*128 + 32*130 + 256)*4)

__global__ __launch_bounds__(256, 1)
void k1_featproj(const float* __restrict__ x,
                 const float* __restrict__ w1, const float* __restrict__ b1,
                 const float* __restrict__ w2, const float* __restrict__ b2,
                 const float* __restrict__ wr, const float* __restrict__ br,
                 const float* __restrict__ g,  const float* __restrict__ be)
{
    extern __shared__ unsigned char smraw[];
    float2* h2 = (float2*)smraw;               // [256][17]
    float2* p2 = h2 + 256*17;                  // [16][17]
    float*  w2s = (float*)(p2 + 16*17);        // [256*128]
    float*  ys  = w2s + 256*128;               // [32][130]
    float*  gs  = ys + 32*130;                 // [128]
    float*  bes = gs + 128;                    // [128]

    int tid = threadIdx.x;
    for (int i = tid; i < 256*128; i += 256) w2s[i] = w2[i];
    if (tid < 128) { gs[tid] = g[tid]; bes[tid] = be[tid]; }

    float w1r[16];
    #pragma unroll
    for (int k = 0; k < 16; k++) w1r[k] = w1[k*256 + tid];
    float b1r = b1[tid];

    int cB = tid & 127, rg = tid >> 7;
    float wrr[16];
    #pragma unroll
    for (int k = 0; k < 16; k++) wrr[k] = wr[k*128 + cB];
    float bB = b2[cB] + br[cB];

    const int NTILES = ROWS_/32;   // 10710
    for (int tile = blockIdx.x; tile < NTILES; tile += gridDim.x) {
        int row0 = tile*32;
        __syncthreads();                                   // (1) protect reuse
        for (int i = tid; i < 32*16; i += 256) {
            int r = i >> 4, k = i & 15;
            int grow = row0 + r;
            int bn = grow / 255, p = grow - bn*255;
            float v = x[bn*L_ + p*8 + k];
            ((float*)(p2 + k*17 + (r>>1)))[r & 1] = v;
        }
        __syncthreads();                                   // (2)

        // phase A: h = relu(patch @ w1 + b1), col = tid, 32 rows packed
        float2 hacc[16];
        #pragma unroll
        for (int rp = 0; rp < 16; rp++) hacc[rp] = make_float2(b1r, b1r);
        #pragma unroll
        for (int k = 0; k < 16; k++) {
            float2 wv = make_float2(w1r[k], w1r[k]);
            #pragma unroll
            for (int rp = 0; rp < 16; rp++)
                hacc[rp] = ffma2(p2[k*17 + rp], wv, hacc[rp]);
        }
        #pragma unroll
        for (int rp = 0; rp < 16; rp++) {
            hacc[rp].x = fmaxf(hacc[rp].x, 0.f);
            hacc[rp].y = fmaxf(hacc[rp].y, 0.f);
        }

        // residual: patch @ wr + (b2+br), col = cB, 16 rows (this rg)
        float2 acc[8];
        #pragma unroll
        for (int j = 0; j < 8; j++) acc[j] = make_float2(bB, bB);
        #pragma unroll
        for (int k = 0; k < 16; k++) {
            float2 wv = make_float2(wrr[k], wrr[k]);
            #pragma unroll
            for (int j = 0; j < 8; j++)
                acc[j] = ffma2(p2[k*17 + rg*8 + j], wv, acc[j]);
        }
        __syncthreads();                                   // (3) prev h2 reads done
        #pragma unroll
        for (int rp = 0; rp < 16; rp++) h2[tid*17 + rp] = hacc[rp];
        __syncthreads();                                   // (4)

        // phase B: y += h @ w2
        #pragma unroll 2
        for (int k = 0; k < 256; k++) {
            float wv = w2s[k*128 + cB];
            float2 wv2 = make_float2(wv, wv);
            #pragma unroll
            for (int j = 0; j < 8; j++)
                acc[j] = ffma2(h2[k*17 + rg*8 + j], wv2, acc[j]);
        }
        #pragma unroll
        for (int j = 0; j < 8; j++) {
            ys[(rg*16 + 2*j  )*130 + cB] = acc[j].x;
            ys[(rg*16 + 2*j+1)*130 + cB] = acc[j].y;
        }
        __syncthreads();                                   // (5)

        // LayerNorm: 8 threads per row
        {
            int r = tid >> 3, seg = tid & 7;
            float s = 0.f, q = 0.f;
            #pragma unroll
            for (int i = 0; i < 16; i++) {
                float v = ys[r*130 + seg*16 + i];
                s += v; q += v*v;
            }
            #pragma unroll
            for (int m = 1; m < 8; m <<= 1) {
                s += __shfl_xor_sync(0xffffffffu, s, m);
                q += __shfl_xor_sync(0xffffffffu, q, m);
            }
            float mu = s * (1.f/128.f);
            float rstd = rsqrtf(q*(1.f/128.f) - mu*mu + EPS_);
            float* outp = g_bufA + (size_t)(row0 + r)*D_ + seg*16;
            #pragma unroll
            for (int i = 0; i < 16; i += 4) {
                float4 o;
                int c = seg*16 + i;
                o.x = (ys[r*130+c+0]-mu)*rstd*gs[c+0] + bes[c+0];
                o.y = (ys[r*130+c+1]-mu)*rstd*gs[c+1] + bes[c+1];
                o.z = (ys[r*130+c+2]-mu)*rstd*gs[c+2] + bes[c+2];
                o.w = (ys[r*130+c+3]-mu)*rstd*gs[c+3] + bes[c+3];
                *(float4*)(outp + i) = o;
            }
        }
    }
}

// =====================================================================
// K2: encoder LEMblock (128->128->128 + res + LN), runs twice
// smem: xh2[128][17] f2 (x then h), w1s/w2s/wrs 64KB each, ys, gs/bes
// =====================================================================
#define SM2_BYTES ((128*17)*8 + (3*128*128 + 32*130 + 256)*4)

__global__ __launch_bounds__(256, 1)
void k2_encoder(const float* __restrict__ ew1, const float* __restrict__ eb1,
                const float* __restrict__ ew2, const float* __restrict__ eb2,
                const float* __restrict__ ewr, const float* __restrict__ ebr,
                const float* __restrict__ eg,  const float* __restrict__ ebe,
                int layer)
{
    extern __shared__ unsigned char smraw[];
    float2* xh2 = (float2*)smraw;              // [128][17]
    float* w1s = (float*)(xh2 + 128*17);
    float* w2s = w1s + 128*128;
    float* wrs = w2s + 128*128;
    float* ys  = wrs + 128*128;                // [32][130]
    float* gs  = ys + 32*130;
    float* bes = gs + 128;

    const float* w1 = ew1 + layer*D_*D_;
    const float* w2 = ew2 + layer*D_*D_;
    const float* wr = ewr + layer*D_*D_;
    const float* zin  = layer ? g_bufB : g_bufA;
    float*       zout = layer ? g_bufA : g_bufB;

    int tid = threadIdx.x;
    for (int i = tid; i < 128*128; i += 256) {
        w1s[i] = w1[i]; w2s[i] = w2[i]; wrs[i] = wr[i];
    }
    if (tid < 128) { gs[tid] = eg[layer*128 + tid]; bes[tid] = ebe[layer*128 + tid]; }
    int cB = tid & 127, rg = tid >> 7;
    float b1r = eb1[layer*128 + cB];
    float bB  = eb2[layer*128 + cB] + ebr[layer*128 + cB];

    const int NTILES = ROWS_/32;
    for (int tile = blockIdx.x; tile < NTILES; tile += gridDim.x) {
        size_t row0 = (size_t)tile*32;
        __syncthreads();                                   // (1)
        for (int i = tid; i < 32*128; i += 256) {
            int r = i >> 7, c = i & 127;
            ((float*)(xh2 + c*17 + (r>>1)))[r & 1] = zin[(row0 + r)*D_ + c];
        }
        __syncthreads();                                   // (2)

        // residual and hidden together (share x loads)
        float2 racc[8], hacc[8];
        #pragma unroll
        for (int j = 0; j < 8; j++) { racc[j] = make_float2(bB, bB); hacc[j] = make_float2(b1r, b1r); }
        #pragma unroll 2
        for (int k = 0; k < 128; k++) {
            float wrv = wrs[k*128 + cB];
            float w1v = w1s[k*128 + cB];
            float2 wr2 = make_float2(wrv, wrv);
            float2 w12 = make_float2(w1v, w1v);
            #pragma unroll
            for (int j = 0; j < 8; j++) {
                float2 xv = xh2[k*17 + rg*8 + j];
                racc[j] = ffma2(xv, wr2, racc[j]);
                hacc[j] = ffma2(xv, w12, hacc[j]);
            }
        }
        #pragma unroll
        for (int j = 0; j < 8; j++) {
            hacc[j].x = fmaxf(hacc[j].x, 0.f);
            hacc[j].y = fmaxf(hacc[j].y, 0.f);
        }
        __syncthreads();                                   // (3) everyone done reading x
        #pragma unroll
        for (int j = 0; j < 8; j++) xh2[cB*17 + rg*8 + j] = hacc[j];
        __syncthreads();                                   // (4)

        // phase B: y = racc + h @ w2
        #pragma unroll 2
        for (int k = 0; k < 128; k++) {
            float wv = w2s[k*128 + cB];
            float2 wv2 = make_float2(wv, wv);
            #pragma unroll
            for (int j = 0; j < 8; j++)
                racc[j] = ffma2(xh2[k*17 + rg*8 + j], wv2, racc[j]);
        }
        #pragma unroll
        for (int j = 0; j < 8; j++) {
            ys[(rg*16 + 2*j  )*130 + cB] = racc[j].x;
            ys[(rg*16 + 2*j+1)*130 + cB] = racc[j].y;
        }
        __syncthreads();                                   // (5)

        {
            int r = tid >> 3, seg = tid & 7;
            float s = 0.f, q = 0.f;
            #pragma unroll
            for (int i = 0; i < 16; i++) {
                float v = ys[r*130 + seg*16 + i];
                s += v; q += v*v;
            }
            #pragma unroll
            for (int m = 1; m < 8; m <<= 1) {
                s += __shfl_xor_sync(0xffffffffu, s, m);
                q += __shfl_xor_sync(0xffffffffu, q, m);
            }
            float mu = s * (1.f/128.f);
            float rstd = rsqrtf(q*(1.f/128.f) - mu*mu + EPS_);
            float* outp = zout + (row0 + r)*D_ + seg*16;
            #pragma unroll
            for (int i = 0; i < 16; i += 4) {
                float4 o;
                int c = seg*16 + i;
                o.x = (ys[r*130+c+0]-mu)*rstd*gs[c+0] + bes[c+0];
                o.y = (ys[r*130+c+1]-mu)*rstd*gs[c+1] + bes[c+1];
                o.z = (ys[r*130+c+2]-mu)*rstd*gs[c+2] + bes[c+2];
                o.w = (ys[r*130+c+3]-mu)*rstd*gs[c+3] + bes[c+3];
                *(float4*)(outp + i) = o;
            }
        }
    }
}

// =====================================================================
// K4: MultiHeadEMA as 2-state linear recurrence + residual + SiLU,
//     transposed write into head layout u[bn][d*255 + t]
// =====================================================================
__global__ void k4_ema(const float* __restrict__ omega)
{
    __shared__ float tile[128*65];
    int bn = blockIdx.x, d = threadIdx.x;
    float q0 = g_ema[d*4+0], a0 = g_ema[d*4+1];
    float q1 = g_ema[d*4+2], a1 = g_ema[d*4+3];
    float om = omega[d];
    const float* src = g_bufA + (size_t)bn*PNUM_*D_ + d;
    float* dst = g_u + (size_t)bn*KHEAD_;
    float s0 = 0.f, s1 = 0.f;
    for (int chunk = 0; chunk < 4; chunk++) {
        int tbase = chunk*64;
        int tn = (PNUM_ - tbase < 64) ? (PNUM_ - tbase) : 64;
        #pragma unroll 4
        for (int i = 0; i < tn; i++) {
            float xv = src[(size_t)(tbase + i)*D_];
            s0 = fmaf(s0, q0, xv);
            s1 = fmaf(s1, q1, xv);
            float v = fmaf(om, xv, fmaf(a0, s0, a1*s1));
            tile[d*65 + i] = v * (1.f/(1.f + __expf(-v)));
        }
        __syncthreads();
        for (int i = d; i < 128*64; i += 128) {
            int dd = i >> 6, tt = i & 63;
            if (tt < tn) dst[dd*PNUM_ + tbase + tt] = tile[dd*65 + tt];
        }
        __syncthreads();
    }
}

// =====================================================================
// K5: head GEMM [1344 x 32640] @ [32640 x 96], K-split=5 with atomics
// =====================================================================
__global__ void k5_init(const float* __restrict__ hb, float* __restrict__ out)
{
    int i = blockIdx.x*blockDim.x + threadIdx.x;
    if (i < BN_*PRED_) out[i] = hb[i % PRED_];
}

__global__ __launch_bounds__(192)
void k5_head(const float* __restrict__ hw, float* __restrict__ out)
{
    __shared__ float2 u2[64*17];
    __shared__ float ws[64*96];
    int tid = threadIdx.x;
    int cB = tid % 96, rg = tid / 96;
    int row0 = blockIdx.x * 32;
    float2 acc[8];
    #pragma unroll
    for (int j = 0; j < 8; j++) acc[j] = make_float2(0.f, 0.f);
    for (int ch = 0; ch < 102; ch++) {
        int k0 = (blockIdx.y * 102 + ch) * 64;
        __syncthreads();
        for (int i = tid; i < 32*64; i += 192) {
            int r = i >> 6, kk = i & 63;
            ((float*)(u2 + kk*17 + (r>>1)))[r & 1] = g_u[(size_t)(row0+r)*KHEAD_ + k0 + kk];
        }
        for (int i = tid; i < 64*96; i += 192) ws[i] = hw[(size_t)k0*96 + i];
        __syncthreads();
        #pragma unroll 2
        for (int kk = 0; kk < 64; kk++) {
            float wv = ws[kk*96 + cB];
            float2 wv2 = make_float2(wv, wv);
            #pragma unroll
            for (int j = 0; j < 8; j++)
                acc[j] = ffma2(u2[kk*17 + rg*8 + j], wv2, acc[j]);
        }
    }
    #pragma unroll
    for (int j = 0; j < 8; j++) {
        int r = row0 + rg*16 + 2*j;
        atomicAdd(&out[r*PRED_ + cB],     acc[j].x);
        atomicAdd(&out[(r+1)*PRED_ + cB], acc[j].y);
    }
}

// =====================================================================
extern "C" void kernel_launch(void* const* d_in, const int* in_sizes, int n_in,
                              void* d_out, int out_size)
{
    const float* x       = (const float*)d_in[0];
    const float* fp_w1   = (const float*)d_in[1];
    const float* fp_b1   = (const float*)d_in[2];
    const float* fp_w2   = (const float*)d_in[3];
    const float* fp_b2   = (const float*)d_in[4];
    const float* fp_wr   = (const float*)d_in[5];
    const float* fp_br   = (const float*)d_in[6];
    const float* fp_g    = (const float*)d_in[7];
    const float* fp_be   = (const float*)d_in[8];
    const float* enc_w1  = (const float*)d_in[9];
    const float* enc_b1  = (const float*)d_in[10];
    const float* enc_w2  = (const float*)d_in[11];
    const float* enc_b2  = (const float*)d_in[12];
    const float* enc_wr  = (const float*)d_in[13];
    const float* enc_br  = (const float*)d_in[14];
    const float* enc_g   = (const float*)d_in[15];
    const float* enc_be  = (const float*)d_in[16];
    const float* e_delta = (const float*)d_in[17];
    const float* e_alpha = (const float*)d_in[18];
    const float* e_beta  = (const float*)d_in[19];
    const float* e_gamma = (const float*)d_in[20];
    const float* e_omega = (const float*)d_in[21];
    const float* head_w  = (const float*)d_in[22];
    const float* head_b  = (const float*)d_in[23];
    float* out = (float*)d_out;

    cudaFuncSetAttribute(k1_featproj, cudaFuncAttributeMaxDynamicSharedMemorySize, SM1_BYTES);
    cudaFuncSetAttribute(k2_encoder,  cudaFuncAttributeMaxDynamicSharedMemorySize, SM2_BYTES);

    k0_emaparam<<<1, 128>>>(e_delta, e_alpha, e_beta, e_gamma);
    k1_featproj<<<148, 256, SM1_BYTES>>>(x, fp_w1, fp_b1, fp_w2, fp_b2, fp_wr, fp_br, fp_g, fp_be);
    k2_encoder<<<148, 256, SM2_BYTES>>>(enc_w1, enc_b1, enc_w2, enc_b2, enc_wr, enc_br, enc_g, enc_be, 0);
    k2_encoder<<<148, 256, SM2_BYTES>>>(enc_w1, enc_b1, enc_w2, enc_b2, enc_wr, enc_br, enc_g, enc_be, 1);
    k4_ema<<<BN_, 128>>>(e_omega);
    k5_init<<<(BN_*PRED_ + 255)/256, 256>>>(head_b, out);
    k5_head<<<dim3(42, 5), 192>>>(head_w, out);
}

// round 4
// speedup vs baseline: 1.6082x; 1.5979x over previous
#include <cuda_runtime.h>
#include <math.h>

#define BN_ 1344
#define L_ 2048
#define PNUM_ 255
#define D_ 128
#define PRED_ 96
#define ROWS_ (BN_*PNUM_)
#define KHEAD_ (D_*PNUM_)
#define EPS_ 1e-5f
#define EMASCALE_ 0.7071067811865476f

__device__ float g_bufA[ROWS_*D_];
__device__ float g_bufB[ROWS_*D_];
__device__ float g_u[(size_t)BN_*KHEAD_];
__device__ float g_ema[D_*4];

__device__ __forceinline__ float2 ffma2(float2 a, float2 b, float2 c) {
    unsigned long long au = *reinterpret_cast<unsigned long long*>(&a);
    unsigned long long bu = *reinterpret_cast<unsigned long long*>(&b);
    unsigned long long cu = *reinterpret_cast<unsigned long long*>(&c);
    unsigned long long ru;
    asm("fma.rn.f32x2 %0, %1, %2, %3;" : "=l"(ru) : "l"(au), "l"(bu), "l"(cu));
    return *reinterpret_cast<float2*>(&ru);
}
__device__ __forceinline__ float2 dup2(float v){ return make_float2(v,v); }

// ============ K0: EMA coefficients ============
__global__ void k0_emaparam(const float* __restrict__ delta, const float* __restrict__ alpha,
                            const float* __restrict__ beta, const float* __restrict__ gamma)
{
    int d = threadIdx.x;
    if (d < D_) {
        #pragma unroll
        for (int n = 0; n < 2; n++) {
            int i = d*2 + n;
            float p = 1.f/(1.f + expf(-delta[i]));
            float q = 1.f - p * (1.f/(1.f + expf(-alpha[i])));
            float a = p * beta[i] * gamma[i] * EMASCALE_;
            g_ema[d*4 + n*2 + 0] = q;
            g_ema[d*4 + n*2 + 1] = a;
        }
    }
}

// ============ K1: featproj (unchanged from R1) ============
#define SM1_BYTES ((256*17 + 16*17)*8 + (256*128 + 32*130 + 256)*4)
__global__ __launch_bounds__(256, 1)
void k1_featproj(const float* __restrict__ x,
                 const float* __restrict__ w1, const float* __restrict__ b1,
                 const float* __restrict__ w2, const float* __restrict__ b2,
                 const float* __restrict__ wr, const float* __restrict__ br,
                 const float* __restrict__ g,  const float* __restrict__ be)
{
    extern __shared__ unsigned char smraw[];
    float2* h2 = (float2*)smraw;
    float2* p2 = h2 + 256*17;
    float*  w2s = (float*)(p2 + 16*17);
    float*  ys  = w2s + 256*128;
    float*  gs  = ys + 32*130;
    float*  bes = gs + 128;

    int tid = threadIdx.x;
    for (int i = tid; i < 256*128; i += 256) w2s[i] = w2[i];
    if (tid < 128) { gs[tid] = g[tid]; bes[tid] = be[tid]; }

    float w1r[16];
    #pragma unroll
    for (int k = 0; k < 16; k++) w1r[k] = w1[k*256 + tid];
    float b1r = b1[tid];
    int cB = tid & 127, rg = tid >> 7;
    float wrr[16];
    #pragma unroll
    for (int k = 0; k < 16; k++) wrr[k] = wr[k*128 + cB];
    float bB = b2[cB] + br[cB];

    const int NTILES = ROWS_/32;
    for (int tile = blockIdx.x; tile < NTILES; tile += gridDim.x) {
        int row0 = tile*32;
        __syncthreads();
        for (int i = tid; i < 32*16; i += 256) {
            int r = i >> 4, k = i & 15;
            int grow = row0 + r;
            int bn = grow / 255, p = grow - bn*255;
            ((float*)(p2 + k*17 + (r>>1)))[r & 1] = x[bn*L_ + p*8 + k];
        }
        __syncthreads();
        float2 hacc[16];
        #pragma unroll
        for (int rp = 0; rp < 16; rp++) hacc[rp] = dup2(b1r);
        #pragma unroll
        for (int k = 0; k < 16; k++) {
            float2 wv = dup2(w1r[k]);
            #pragma unroll
            for (int rp = 0; rp < 16; rp++)
                hacc[rp] = ffma2(p2[k*17 + rp], wv, hacc[rp]);
        }
        #pragma unroll
        for (int rp = 0; rp < 16; rp++) {
            hacc[rp].x = fmaxf(hacc[rp].x, 0.f);
            hacc[rp].y = fmaxf(hacc[rp].y, 0.f);
        }
        float2 acc[8];
        #pragma unroll
        for (int j = 0; j < 8; j++) acc[j] = dup2(bB);
        #pragma unroll
        for (int k = 0; k < 16; k++) {
            float2 wv = dup2(wrr[k]);
            #pragma unroll
            for (int j = 0; j < 8; j++)
                acc[j] = ffma2(p2[k*17 + rg*8 + j], wv, acc[j]);
        }
        __syncthreads();
        #pragma unroll
        for (int rp = 0; rp < 16; rp++) h2[tid*17 + rp] = hacc[rp];
        __syncthreads();
        #pragma unroll 2
        for (int k = 0; k < 256; k++) {
            float2 wv2 = dup2(w2s[k*128 + cB]);
            #pragma unroll
            for (int j = 0; j < 8; j++)
                acc[j] = ffma2(h2[k*17 + rg*8 + j], wv2, acc[j]);
        }
        #pragma unroll
        for (int j = 0; j < 8; j++) {
            ys[(rg*16 + 2*j  )*130 + cB] = acc[j].x;
            ys[(rg*16 + 2*j+1)*130 + cB] = acc[j].y;
        }
        __syncthreads();
        {
            int r = tid >> 3, seg = tid & 7;
            float s = 0.f, q = 0.f;
            #pragma unroll
            for (int i = 0; i < 16; i++) {
                float v = ys[r*130 + seg*16 + i];
                s += v; q += v*v;
            }
            #pragma unroll
            for (int m = 1; m < 8; m <<= 1) {
                s += __shfl_xor_sync(0xffffffffu, s, m);
                q += __shfl_xor_sync(0xffffffffu, q, m);
            }
            float mu = s * (1.f/128.f);
            float rstd = rsqrtf(q*(1.f/128.f) - mu*mu + EPS_);
            float* outp = g_bufA + (size_t)(row0 + r)*D_ + seg*16;
            #pragma unroll
            for (int i = 0; i < 16; i += 4) {
                float4 o;
                int c = seg*16 + i;
                o.x = (ys[r*130+c+0]-mu)*rstd*gs[c+0] + bes[c+0];
                o.y = (ys[r*130+c+1]-mu)*rstd*gs[c+1] + bes[c+1];
                o.z = (ys[r*130+c+2]-mu)*rstd*gs[c+2] + bes[c+2];
                o.w = (ys[r*130+c+3]-mu)*rstd*gs[c+3] + bes[c+3];
                *(float4*)(outp + i) = o;
            }
        }
    }
}

// ============ K2: encoder, 2-D register blocking ============
// 256 thr, 64-row x 128-col tile, 4x8 per thread.
// smem: w1p/w2p/wrp [128][64] f2 permuted, xs [128][32] f2 swizzled, biases.
#define SM2_BYTES (3*128*64*8 + 128*32*8 + 4*128*4)

__global__ __launch_bounds__(256, 1)
void k2_encoder(const float* __restrict__ ew1, const float* __restrict__ eb1,
                const float* __restrict__ ew2, const float* __restrict__ eb2,
                const float* __restrict__ ewr, const float* __restrict__ ebr,
                const float* __restrict__ eg,  const float* __restrict__ ebe,
                int layer)
{
    extern __shared__ unsigned char smraw[];
    float2* w1p = (float2*)smraw;          // [128][64]: slot j*16+cg = colpair cg*4+j
    float2* w2p = w1p + 128*64;
    float2* wrp = w2p + 128*64;
    float2* xs2 = wrp + 128*64;            // [128][32] rowpairs, swizzled by (k&31)
    float*  b1s = (float*)(xs2 + 128*32);
    float*  bBs = b1s + 128;
    float*  gs  = bBs + 128;
    float*  bes = gs + 128;
    float*  xsf = (float*)xs2;

    const float* w1 = ew1 + layer*D_*D_;
    const float* w2 = ew2 + layer*D_*D_;
    const float* wr = ewr + layer*D_*D_;
    const float* zin  = layer ? g_bufB : g_bufA;
    float*       zout = layer ? g_bufA : g_bufB;

    int tid = threadIdx.x;
    for (int idx = tid; idx < 128*64; idx += 256) {
        int k = idx >> 6, s = idx & 63;
        int p = (s & 15)*4 + (s >> 4);     // colpair
        w1p[idx] = *(const float2*)(w1 + k*128 + 2*p);
        w2p[idx] = *(const float2*)(w2 + k*128 + 2*p);
        wrp[idx] = *(const float2*)(wr + k*128 + 2*p);
    }
    if (tid < 128) {
        b1s[tid] = eb1[layer*128 + tid];
        bBs[tid] = eb2[layer*128 + tid] + ebr[layer*128 + tid];
        gs[tid]  = eg[layer*128 + tid];
        bes[tid] = ebe[layer*128 + tid];
    }

    int cg = tid & 15, rg = tid >> 4;      // 16 colgroups x 16 rowgroups
    int c0 = cg*8, p0 = rg*2;              // 8 cols, rowpairs p0,p0+1 (4 rows)

    const int NTILES = ROWS_/64;           // 5355 exact
    for (int tile = blockIdx.x; tile < NTILES; tile += gridDim.x) {
        int row0 = tile*64;
        __syncthreads();
        // transpose-in: 4 threads/row, 32 cols each
        {
            int r = tid >> 2, q0 = (tid & 3)*32;
            const float* src = zin + (size_t)(row0 + r)*D_ + q0;
            int rp = r >> 1, h = r & 1;
            #pragma unroll
            for (int q4 = 0; q4 < 32; q4 += 4) {
                float4 v = *(const float4*)(src + q4);
                int c = q0 + q4;
                xsf[((c  )*32 + (rp ^ ((c  )&31)))*2 + h] = v.x;
                xsf[((c+1)*32 + (rp ^ ((c+1)&31)))*2 + h] = v.y;
                xsf[((c+2)*32 + (rp ^ ((c+2)&31)))*2 + h] = v.z;
                xsf[((c+3)*32 + (rp ^ ((c+3)&31)))*2 + h] = v.w;
            }
        }
        __syncthreads();

        // phase A+R: h = relu(x@w1+b1), rc = x@wr+bB
        float2 ha[2][8], rc[2][8];
        #pragma unroll
        for (int i = 0; i < 2; i++)
            #pragma unroll
            for (int j = 0; j < 8; j++) { ha[i][j] = dup2(b1s[c0+j]); rc[i][j] = dup2(bBs[c0+j]); }
        #pragma unroll 2
        for (int k = 0; k < 128; k++) {
            int sk = k & 31;
            float2 xv0 = xs2[k*32 + ((p0  ) ^ sk)];
            float2 xv1 = xs2[k*32 + ((p0+1) ^ sk)];
            #pragma unroll
            for (int j = 0; j < 4; j++) {
                float2 wv = w1p[k*64 + j*16 + cg];
                float2 uv = wrp[k*64 + j*16 + cg];
                float2 wa = dup2(wv.x), wb = dup2(wv.y);
                float2 ua = dup2(uv.x), ub = dup2(uv.y);
                ha[0][2*j]   = ffma2(xv0, wa, ha[0][2*j]);
                ha[1][2*j]   = ffma2(xv1, wa, ha[1][2*j]);
                ha[0][2*j+1] = ffma2(xv0, wb, ha[0][2*j+1]);
                ha[1][2*j+1] = ffma2(xv1, wb, ha[1][2*j+1]);
                rc[0][2*j]   = ffma2(xv0, ua, rc[0][2*j]);
                rc[1][2*j]   = ffma2(xv1, ua, rc[1][2*j]);
                rc[0][2*j+1] = ffma2(xv0, ub, rc[0][2*j+1]);
                rc[1][2*j+1] = ffma2(xv1, ub, rc[1][2*j+1]);
            }
        }
        __syncthreads();   // all x reads done
        // relu + store h over x buffer
        #pragma unroll
        for (int i = 0; i < 2; i++)
            #pragma unroll
            for (int j = 0; j < 8; j++) {
                float2 v = ha[i][j];
                v.x = fmaxf(v.x, 0.f); v.y = fmaxf(v.y, 0.f);
                int c = c0 + j;
                xs2[c*32 + ((p0+i) ^ (c&31))] = v;
            }
        __syncthreads();

        // phase B: rc += h @ w2
        #pragma unroll 2
        for (int k = 0; k < 128; k++) {
            int sk = k & 31;
            float2 xv0 = xs2[k*32 + ((p0  ) ^ sk)];
            float2 xv1 = xs2[k*32 + ((p0+1) ^ sk)];
            #pragma unroll
            for (int j = 0; j < 4; j++) {
                float2 wv = w2p[k*64 + j*16 + cg];
                float2 wa = dup2(wv.x), wb = dup2(wv.y);
                rc[0][2*j]   = ffma2(xv0, wa, rc[0][2*j]);
                rc[1][2*j]   = ffma2(xv1, wa, rc[1][2*j]);
                rc[0][2*j+1] = ffma2(xv0, wb, rc[0][2*j+1]);
                rc[1][2*j+1] = ffma2(xv1, wb, rc[1][2*j+1]);
            }
        }

        // register LayerNorm (sum across 16 cg lanes) + store
        #pragma unroll
        for (int i = 0; i < 2; i++) {
            float2 s = rc[i][0];
            float2 q = make_float2(rc[i][0].x*rc[i][0].x, rc[i][0].y*rc[i][0].y);
            #pragma unroll
            for (int j = 1; j < 8; j++) {
                s.x += rc[i][j].x; s.y += rc[i][j].y;
                q.x = fmaf(rc[i][j].x, rc[i][j].x, q.x);
                q.y = fmaf(rc[i][j].y, rc[i][j].y, q.y);
            }
            #pragma unroll
            for (int m = 1; m < 16; m <<= 1) {
                s.x += __shfl_xor_sync(0xffffffffu, s.x, m);
                s.y += __shfl_xor_sync(0xffffffffu, s.y, m);
                q.x += __shfl_xor_sync(0xffffffffu, q.x, m);
                q.y += __shfl_xor_sync(0xffffffffu, q.y, m);
            }
            float mux = s.x*(1.f/128.f), muy = s.y*(1.f/128.f);
            float rsx = rsqrtf(q.x*(1.f/128.f) - mux*mux + EPS_);
            float rsy = rsqrtf(q.y*(1.f/128.f) - muy*muy + EPS_);
            size_t grow = (size_t)row0 + 2*(p0+i);
            float* op0 = zout + grow*D_ + c0;
            float* op1 = op0 + D_;
            float4 a0, b0, a1, b1;
            a0.x=(rc[i][0].x-mux)*rsx*gs[c0+0]+bes[c0+0]; a0.y=(rc[i][1].x-mux)*rsx*gs[c0+1]+bes[c0+1];
            a0.z=(rc[i][2].x-mux)*rsx*gs[c0+2]+bes[c0+2]; a0.w=(rc[i][3].x-mux)*rsx*gs[c0+3]+bes[c0+3];
            b0.x=(rc[i][4].x-mux)*rsx*gs[c0+4]+bes[c0+4]; b0.y=(rc[i][5].x-mux)*rsx*gs[c0+5]+bes[c0+5];
            b0.z=(rc[i][6].x-mux)*rsx*gs[c0+6]+bes[c0+6]; b0.w=(rc[i][7].x-mux)*rsx*gs[c0+7]+bes[c0+7];
            a1.x=(rc[i][0].y-muy)*rsy*gs[c0+0]+bes[c0+0]; a1.y=(rc[i][1].y-muy)*rsy*gs[c0+1]+bes[c0+1];
            a1.z=(rc[i][2].y-muy)*rsy*gs[c0+2]+bes[c0+2]; a1.w=(rc[i][3].y-muy)*rsy*gs[c0+3]+bes[c0+3];
            b1.x=(rc[i][4].y-muy)*rsy*gs[c0+4]+bes[c0+4]; b1.y=(rc[i][5].y-muy)*rsy*gs[c0+5]+bes[c0+5];
            b1.z=(rc[i][6].y-muy)*rsy*gs[c0+6]+bes[c0+6]; b1.w=(rc[i][7].y-muy)*rsy*gs[c0+7]+bes[c0+7];
            *(float4*)(op0) = a0; *(float4*)(op0+4) = b0;
            *(float4*)(op1) = a1; *(float4*)(op1+4) = b1;
        }
    }
}

// ============ K4: EMA recurrence (unchanged) ============
__global__ void k4_ema(const float* __restrict__ omega)
{
    __shared__ float tile[128*65];
    int bn = blockIdx.x, d = threadIdx.x;
    float q0 = g_ema[d*4+0], a0 = g_ema[d*4+1];
    float q1 = g_ema[d*4+2], a1 = g_ema[d*4+3];
    float om = omega[d];
    const float* src = g_bufA + (size_t)bn*PNUM_*D_ + d;
    float* dst = g_u + (size_t)bn*KHEAD_;
    float s0 = 0.f, s1 = 0.f;
    for (int chunk = 0; chunk < 4; chunk++) {
        int tbase = chunk*64;
        int tn = (PNUM_ - tbase < 64) ? (PNUM_ - tbase) : 64;
        #pragma unroll 4
        for (int i = 0; i < tn; i++) {
            float xv = src[(size_t)(tbase + i)*D_];
            s0 = fmaf(s0, q0, xv);
            s1 = fmaf(s1, q1, xv);
            float v = fmaf(om, xv, fmaf(a0, s0, a1*s1));
            tile[d*65 + i] = v * (1.f/(1.f + __expf(-v)));
        }
        __syncthreads();
        for (int i = d; i < 128*64; i += 128) {
            int dd = i >> 6, tt = i & 63;
            if (tt < tn) dst[dd*PNUM_ + tbase + tt] = tile[dd*65 + tt];
        }
        __syncthreads();
    }
}

// ============ K5: head GEMM (unchanged) ============
__global__ void k5_init(const float* __restrict__ hb, float* __restrict__ out)
{
    int i = blockIdx.x*blockDim.x + threadIdx.x;
    if (i < BN_*PRED_) out[i] = hb[i % PRED_];
}

__global__ __launch_bounds__(192)
void k5_head(const float* __restrict__ hw, float* __restrict__ out)
{
    __shared__ float2 u2[64*17];
    __shared__ float ws[64*96];
    int tid = threadIdx.x;
    int cB = tid % 96, rg = tid / 96;
    int row0 = blockIdx.x * 32;
    float2 acc[8];
    #pragma unroll
    for (int j = 0; j < 8; j++) acc[j] = make_float2(0.f, 0.f);
    for (int ch = 0; ch < 102; ch++) {
        int k0 = (blockIdx.y * 102 + ch) * 64;
        __syncthreads();
        for (int i = tid; i < 32*64; i += 192) {
            int r = i >> 6, kk = i & 63;
            ((float*)(u2 + kk*17 + (r>>1)))[r & 1] = g_u[(size_t)(row0+r)*KHEAD_ + k0 + kk];
        }
        for (int i = tid; i < 64*96; i += 192) ws[i] = hw[(size_t)k0*96 + i];
        __syncthreads();
        #pragma unroll 2
        for (int kk = 0; kk < 64; kk++) {
            float2 wv2 = make_float2(ws[kk*96 + cB], ws[kk*96 + cB]);
            #pragma unroll
            for (int j = 0; j < 8; j++)
                acc[j] = ffma2(u2[kk*17 + rg*8 + j], wv2, acc[j]);
        }
    }
    #pragma unroll
    for (int j = 0; j < 8; j++) {
        int r = row0 + rg*16 + 2*j;
        atomicAdd(&out[r*PRED_ + cB],     acc[j].x);
        atomicAdd(&out[(r+1)*PRED_ + cB], acc[j].y);
    }
}

// ============ launch ============
extern "C" void kernel_launch(void* const* d_in, const int* in_sizes, int n_in,
                              void* d_out, int out_size)
{
    const float* x       = (const float*)d_in[0];
    const float* fp_w1   = (const float*)d_in[1];
    const float* fp_b1   = (const float*)d_in[2];
    const float* fp_w2   = (const float*)d_in[3];
    const float* fp_b2   = (const float*)d_in[4];
    const float* fp_wr   = (const float*)d_in[5];
    const float* fp_br   = (const float*)d_in[6];
    const float* fp_g    = (const float*)d_in[7];
    const float* fp_be   = (const float*)d_in[8];
    const float* enc_w1  = (const float*)d_in[9];
    const float* enc_b1  = (const float*)d_in[10];
    const float* enc_w2  = (const float*)d_in[11];
    const float* enc_b2  = (const float*)d_in[12];
    const float* enc_wr  = (const float*)d_in[13];
    const float* enc_br  = (const float*)d_in[14];
    const float* enc_g   = (const float*)d_in[15];
    const float* enc_be  = (const float*)d_in[16];
    const float* e_delta = (const float*)d_in[17];
    const float* e_alpha = (const float*)d_in[18];
    const float* e_beta  = (const float*)d_in[19];
    const float* e_gamma = (const float*)d_in[20];
    const float* e_omega = (const float*)d_in[21];
    const float* head_w  = (const float*)d_in[22];
    const float* head_b  = (const float*)d_in[23];
    float* out = (float*)d_out;

    cudaFuncSetAttribute(k1_featproj, cudaFuncAttributeMaxDynamicSharedMemorySize, SM1_BYTES);
    cudaFuncSetAttribute(k2_encoder,  cudaFuncAttributeMaxDynamicSharedMemorySize, SM2_BYTES);

    k0_emaparam<<<1, 128>>>(e_delta, e_alpha, e_beta, e_gamma);
    k1_featproj<<<148, 256, SM1_BYTES>>>(x, fp_w1, fp_b1, fp_w2, fp_b2, fp_wr, fp_br, fp_g, fp_be);
    k2_encoder<<<148, 256, SM2_BYTES>>>(enc_w1, enc_b1, enc_w2, enc_b2, enc_wr, enc_br, enc_g, enc_be, 0);
    k2_encoder<<<148, 256, SM2_BYTES>>>(enc_w1, enc_b1, enc_w2, enc_b2, enc_wr, enc_br, enc_g, enc_be, 1);
    k4_ema<<<BN_, 128>>>(e_omega);
    k5_init<<<(BN_*PRED_ + 255)/256, 256>>>(head_b, out);
    k5_head<<<dim3(42, 5), 192>>>(head_w, out);
}

// round 6
// speedup vs baseline: 2.3110x; 1.4370x over previous
#include <cuda_runtime.h>
#include <math.h>

#define BN_ 1344
#define L_ 2048
#define PNUM_ 255
#define D_ 128
#define PRED_ 96
#define ROWS_ (BN_*PNUM_)      /* 342720 = 64*5355 */
#define KHEAD_ (D_*PNUM_)      /* 32640 */
#define EPS_ 1e-5f
#define EMASCALE_ 0.7071067811865476f
#define SWR(c) ((((c)>>3)&3)*8)
#define SWH(c) (((((c)>>3)&3)*8) ^ ((((c)>>5)&3)*4))

__device__ float g_bufA[ROWS_*D_];
__device__ float g_bufB[ROWS_*D_];
__device__ float g_u[(size_t)BN_*KHEAD_];
__device__ float g_ema[D_*4];

__device__ __forceinline__ float2 ffma2(float2 a, float2 b, float2 c) {
    unsigned long long au = *reinterpret_cast<unsigned long long*>(&a);
    unsigned long long bu = *reinterpret_cast<unsigned long long*>(&b);
    unsigned long long cu = *reinterpret_cast<unsigned long long*>(&c);
    unsigned long long ru;
    asm("fma.rn.f32x2 %0, %1, %2, %3;" : "=l"(ru) : "l"(au), "l"(bu), "l"(cu));
    return *reinterpret_cast<float2*>(&ru);
}
__device__ __forceinline__ float2 dup2(float v){ return make_float2(v,v); }

// ============ K0: EMA coefficients ============
__global__ void k0_emaparam(const float* __restrict__ delta, const float* __restrict__ alpha,
                            const float* __restrict__ beta, const float* __restrict__ gamma)
{
    int d = threadIdx.x;
    if (d < D_) {
        #pragma unroll
        for (int n = 0; n < 2; n++) {
            int i = d*2 + n;
            float p = 1.f/(1.f + expf(-delta[i]));
            float q = 1.f - p * (1.f/(1.f + expf(-alpha[i])));
            float a = p * beta[i] * gamma[i] * EMASCALE_;
            g_ema[d*4 + n*2 + 0] = q;
            g_ema[d*4 + n*2 + 1] = a;
        }
    }
}

// ============ K1: featproj LEMblock 16->256->128, 64-row tiles ============
// smem: w1p f2[16][128], wrp f2[16][64], w2p f2[256][64],
//       xs1 f[16][64], hs1 f[256][64], params 640 f
#define SM1_BYTES (16*128*8 + 16*64*8 + 256*64*8 + 16*64*4 + 256*64*4 + 640*4)

__global__ __launch_bounds__(256, 1)
void k1_featproj(const float* __restrict__ x,
                 const float* __restrict__ w1, const float* __restrict__ b1,
                 const float* __restrict__ w2, const float* __restrict__ b2,
                 const float* __restrict__ wr, const float* __restrict__ br,
                 const float* __restrict__ g,  const float* __restrict__ be)
{
    extern __shared__ unsigned char smraw[];
    float2* w1p = (float2*)smraw;              // [16][128] slot j*32+cg <-> cp=cg*4+j
    float2* wrp = w1p + 16*128;                // [16][64]  slot j*16+cg <-> cp=cg*4+j
    float2* w2p = wrp + 16*64;                 // [256][64] slot j*16+cg
    float*  xs1 = (float*)(w2p + 256*64);      // [16][64]
    float*  hs1 = xs1 + 16*64;                 // [256][64]
    float*  b1s = hs1 + 256*64;                // [256]
    float*  bBs = b1s + 256;                   // [128]
    float*  gs  = bBs + 128;
    float*  bes = gs + 128;

    int tid = threadIdx.x;
    const float2* w1g = (const float2*)w1;
    const float2* wrg = (const float2*)wr;
    const float2* w2g = (const float2*)w2;
    for (int i = tid; i < 16*128; i += 256) {
        int k = i >> 7, s = i & 127;
        w1p[i] = w1g[k*128 + (s & 31)*4 + (s >> 5)];
    }
    for (int i = tid; i < 16*64; i += 256) {
        int k = i >> 6, s = i & 63;
        wrp[i] = wrg[k*64 + (s & 15)*4 + (s >> 4)];
    }
    for (int i = tid; i < 256*64; i += 256) {
        int k = i >> 6, s = i & 63;
        w2p[i] = w2g[k*64 + (s & 15)*4 + (s >> 4)];
    }
    if (tid < 256) b1s[tid] = b1[tid];
    if (tid < 128) { bBs[tid] = b2[tid] + br[tid]; gs[tid] = g[tid]; bes[tid] = be[tid]; }
    __syncthreads();

    int cgA = tid & 31, rgA = tid >> 5;        // phase A: 32x8
    int c0A = cgA*8, r0A = rgA*8;
    int cgB = tid & 15, rgB = tid >> 4;        // phase B: 16x16
    int c0B = cgB*8, r0B = rgB*4;

    float2 bhA[4], byB[4], gv[4], bev[4];
    #pragma unroll
    for (int j = 0; j < 4; j++) {
        bhA[j] = *(float2*)(b1s + c0A + 2*j);
        byB[j] = *(float2*)(bBs + c0B + 2*j);
        gv[j]  = *(float2*)(gs  + c0B + 2*j);
        bev[j] = *(float2*)(bes + c0B + 2*j);
    }

    const int NTILES = ROWS_/64;               // 5355
    for (int tile = blockIdx.x; tile < NTILES; tile += gridDim.x) {
        int row0 = tile*64;
        __syncthreads();                       // (1)
        // patch gather -> xs1[c][r]
        {
            int r = tid >> 2, q = (tid & 3)*4;
            int grow = row0 + r;
            int bn = grow/255, p = grow - bn*255;
            float4 v = *(const float4*)(x + bn*L_ + p*8 + q);
            xs1[(q+0)*64 + r] = v.x;
            xs1[(q+1)*64 + r] = v.y;
            xs1[(q+2)*64 + r] = v.z;
            xs1[(q+3)*64 + r] = v.w;
        }
        __syncthreads();                       // (2)

        // phase A: h[64x256] = relu(x@w1+b1); store hs1. (layout A)
        {
            float2 ha[8][4];
            #pragma unroll
            for (int i = 0; i < 8; i++)
                #pragma unroll
                for (int j = 0; j < 4; j++) ha[i][j] = bhA[j];
            #pragma unroll
            for (int k = 0; k < 16; k++) {
                float4 xa = *(const float4*)(xs1 + k*64 + r0A);
                float4 xb = *(const float4*)(xs1 + k*64 + r0A + 4);
                float2 xd[8] = {dup2(xa.x),dup2(xa.y),dup2(xa.z),dup2(xa.w),
                                dup2(xb.x),dup2(xb.y),dup2(xb.z),dup2(xb.w)};
                #pragma unroll
                for (int j = 0; j < 4; j++) {
                    float2 wv = w1p[k*128 + j*32 + cgA];
                    #pragma unroll
                    for (int i = 0; i < 8; i++) ha[i][j] = ffma2(xd[i], wv, ha[i][j]);
                }
            }
            #pragma unroll
            for (int j = 0; j < 4; j++) {
                int ca = c0A + 2*j, cb = ca + 1;
                float4 va0 = make_float4(fmaxf(ha[0][j].x,0.f),fmaxf(ha[1][j].x,0.f),fmaxf(ha[2][j].x,0.f),fmaxf(ha[3][j].x,0.f));
                float4 va1 = make_float4(fmaxf(ha[4][j].x,0.f),fmaxf(ha[5][j].x,0.f),fmaxf(ha[6][j].x,0.f),fmaxf(ha[7][j].x,0.f));
                float4 vb0 = make_float4(fmaxf(ha[0][j].y,0.f),fmaxf(ha[1][j].y,0.f),fmaxf(ha[2][j].y,0.f),fmaxf(ha[3][j].y,0.f));
                float4 vb1 = make_float4(fmaxf(ha[4][j].y,0.f),fmaxf(ha[5][j].y,0.f),fmaxf(ha[6][j].y,0.f),fmaxf(ha[7][j].y,0.f));
                *(float4*)(hs1 + ca*64 + (r0A     ^ SWH(ca))) = va0;
                *(float4*)(hs1 + ca*64 + ((r0A+4) ^ SWH(ca))) = va1;
                *(float4*)(hs1 + cb*64 + (r0B*0 + (r0A     ^ SWH(cb)))) = vb0;
                *(float4*)(hs1 + cb*64 + ((r0A+4) ^ SWH(cb))) = vb1;
            }
        }
        // residual (layout B): rc = x @ wr + bB
        float2 rc[4][4];
        #pragma unroll
        for (int i = 0; i < 4; i++)
            #pragma unroll
            for (int j = 0; j < 4; j++) rc[i][j] = byB[j];
        #pragma unroll
        for (int k = 0; k < 16; k++) {
            float4 xa = *(const float4*)(xs1 + k*64 + r0B);
            float2 xd[4] = {dup2(xa.x),dup2(xa.y),dup2(xa.z),dup2(xa.w)};
            #pragma unroll
            for (int j = 0; j < 4; j++) {
                float2 wv = wrp[k*64 + j*16 + cgB];
                #pragma unroll
                for (int i = 0; i < 4; i++) rc[i][j] = ffma2(xd[i], wv, rc[i][j]);
            }
        }
        __syncthreads();                       // (3) hs1 visible

        // phase B: rc += h @ w2 (layout B)
        #pragma unroll 4
        for (int k = 0; k < 256; k++) {
            float4 xa = *(const float4*)(hs1 + k*64 + (r0B ^ SWH(k)));
            float2 xd[4] = {dup2(xa.x),dup2(xa.y),dup2(xa.z),dup2(xa.w)};
            #pragma unroll
            for (int j = 0; j < 4; j++) {
                float2 wv = w2p[k*64 + j*16 + cgB];
                #pragma unroll
                for (int i = 0; i < 4; i++) rc[i][j] = ffma2(xd[i], wv, rc[i][j]);
            }
        }
        // LN + store
        #pragma unroll
        for (int i = 0; i < 4; i++) {
            float s = 0.f, q = 0.f;
            #pragma unroll
            for (int j = 0; j < 4; j++) {
                s += rc[i][j].x + rc[i][j].y;
                q += rc[i][j].x*rc[i][j].x + rc[i][j].y*rc[i][j].y;
            }
            #pragma unroll
            for (int m = 1; m < 16; m <<= 1) {
                s += __shfl_xor_sync(0xffffffffu, s, m);
                q += __shfl_xor_sync(0xffffffffu, q, m);
            }
            float mu = s*(1.f/128.f);
            float rs = rsqrtf(q*(1.f/128.f) - mu*mu + EPS_);
            float o[8];
            #pragma unroll
            for (int j = 0; j < 4; j++) {
                o[2*j]   = (rc[i][j].x - mu)*rs*gv[j].x + bev[j].x;
                o[2*j+1] = (rc[i][j].y - mu)*rs*gv[j].y + bev[j].y;
            }
            float* op = g_bufA + (size_t)(row0 + r0B + i)*D_ + c0B;
            *(float4*)op     = make_float4(o[0],o[1],o[2],o[3]);
            *(float4*)(op+4) = make_float4(o[4],o[5],o[6],o[7]);
        }
    }
}

// ============ K2: encoder LEMblock 128->128->128, 64-row tiles ============
// smem: w1p/wrp/w2p f2[128][64], xs f[128][64], params
#define SM2_BYTES (3*128*64*8 + 128*64*4 + 512*4)

__global__ __launch_bounds__(256, 1)
void k2_encoder(const float* __restrict__ ew1, const float* __restrict__ eb1,
                const float* __restrict__ ew2, const float* __restrict__ eb2,
                const float* __restrict__ ewr, const float* __restrict__ ebr,
                const float* __restrict__ eg,  const float* __restrict__ ebe,
                int layer)
{
    extern __shared__ unsigned char smraw[];
    float2* w1p = (float2*)smraw;              // [128][64] slot j*16+cg <-> cp=cg*4+j
    float2* wrp = w1p + 128*64;
    float2* w2p = wrp + 128*64;
    float*  xs  = (float*)(w2p + 128*64);      // [128][64]
    float*  b1s = xs + 128*64;
    float*  bBs = b1s + 128;
    float*  gs  = bBs + 128;
    float*  bes = gs + 128;

    const float2* w1g = (const float2*)(ew1 + layer*D_*D_);
    const float2* wrg = (const float2*)(ewr + layer*D_*D_);
    const float2* w2g = (const float2*)(ew2 + layer*D_*D_);
    const float* zin  = layer ? g_bufB : g_bufA;
    float*       zout = layer ? g_bufA : g_bufB;

    int tid = threadIdx.x;
    for (int i = tid; i < 128*64; i += 256) {
        int k = i >> 6, s = i & 63;
        int p = (s & 15)*4 + (s >> 4);
        w1p[i] = w1g[k*64 + p];
        wrp[i] = wrg[k*64 + p];
        w2p[i] = w2g[k*64 + p];
    }
    if (tid < 128) {
        b1s[tid] = eb1[layer*128 + tid];
        bBs[tid] = eb2[layer*128 + tid] + ebr[layer*128 + tid];
        gs[tid]  = eg[layer*128 + tid];
        bes[tid] = ebe[layer*128 + tid];
    }
    __syncthreads();

    int cg = tid & 15, rg = tid >> 4;          // 16 x 16
    int c0 = cg*8, r0 = rg*4;
    float2 bh[4], by[4], gv[4], bev[4];
    #pragma unroll
    for (int j = 0; j < 4; j++) {
        bh[j]  = *(float2*)(b1s + c0 + 2*j);
        by[j]  = *(float2*)(bBs + c0 + 2*j);
        gv[j]  = *(float2*)(gs  + c0 + 2*j);
        bev[j] = *(float2*)(bes + c0 + 2*j);
    }

    const int NTILES = ROWS_/64;               // 5355
    for (int tile = blockIdx.x; tile < NTILES; tile += gridDim.x) {
        int row0 = tile*64;
        __syncthreads();                       // (1)
        // transpose-in: xs[c][r ^ SWR(c)]
        {
            int r = tid >> 2, q0 = (tid & 3)*32;
            const float* src = zin + (size_t)(row0 + r)*D_ + q0;
            #pragma unroll
            for (int q4 = 0; q4 < 32; q4 += 4) {
                float4 v = *(const float4*)(src + q4);
                int c = q0 + q4;
                int rr = r ^ SWR(c);
                xs[(c+0)*64 + rr] = v.x;
                xs[(c+1)*64 + rr] = v.y;
                xs[(c+2)*64 + rr] = v.z;
                xs[(c+3)*64 + rr] = v.w;
            }
        }
        __syncthreads();                       // (2)

        // phase A: ha = x@w1, rc = x@wr
        float2 ha[4][4], rc[4][4];
        #pragma unroll
        for (int i = 0; i < 4; i++)
            #pragma unroll
            for (int j = 0; j < 4; j++) { ha[i][j] = bh[j]; rc[i][j] = by[j]; }
        #pragma unroll 4
        for (int k = 0; k < 128; k++) {
            float4 xv = *(const float4*)(xs + k*64 + (r0 ^ SWR(k)));
            float2 xd[4] = {dup2(xv.x),dup2(xv.y),dup2(xv.z),dup2(xv.w)};
            #pragma unroll
            for (int j = 0; j < 4; j++) {
                float2 w1v = w1p[k*64 + j*16 + cg];
                float2 wrv = wrp[k*64 + j*16 + cg];
                #pragma unroll
                for (int i = 0; i < 4; i++) {
                    ha[i][j] = ffma2(xd[i], w1v, ha[i][j]);
                    rc[i][j] = ffma2(xd[i], wrv, rc[i][j]);
                }
            }
        }
        __syncthreads();                       // (3) x reads done
        // store relu(h) over xs
        #pragma unroll
        for (int j = 0; j < 4; j++) {
            int ca = c0 + 2*j, cb = ca + 1;
            float4 va = make_float4(fmaxf(ha[0][j].x,0.f),fmaxf(ha[1][j].x,0.f),fmaxf(ha[2][j].x,0.f),fmaxf(ha[3][j].x,0.f));
            float4 vb = make_float4(fmaxf(ha[0][j].y,0.f),fmaxf(ha[1][j].y,0.f),fmaxf(ha[2][j].y,0.f),fmaxf(ha[3][j].y,0.f));
            *(float4*)(xs + ca*64 + (r0 ^ SWR(ca))) = va;
            *(float4*)(xs + cb*64 + (r0 ^ SWR(cb))) = vb;
        }
        __syncthreads();                       // (4)

        // phase B: rc += h @ w2
        #pragma unroll 4
        for (int k = 0; k < 128; k++) {
            float4 xv = *(const float4*)(xs + k*64 + (r0 ^ SWR(k)));
            float2 xd[4] = {dup2(xv.x),dup2(xv.y),dup2(xv.z),dup2(xv.w)};
            #pragma unroll
            for (int j = 0; j < 4; j++) {
                float2 wv = w2p[k*64 + j*16 + cg];
                #pragma unroll
                for (int i = 0; i < 4; i++) rc[i][j] = ffma2(xd[i], wv, rc[i][j]);
            }
        }
        // LN + store
        #pragma unroll
        for (int i = 0; i < 4; i++) {
            float s = 0.f, q = 0.f;
            #pragma unroll
            for (int j = 0; j < 4; j++) {
                s += rc[i][j].x + rc[i][j].y;
                q += rc[i][j].x*rc[i][j].x + rc[i][j].y*rc[i][j].y;
            }
            #pragma unroll
            for (int m = 1; m < 16; m <<= 1) {
                s += __shfl_xor_sync(0xffffffffu, s, m);
                q += __shfl_xor_sync(0xffffffffu, q, m);
            }
            float mu = s*(1.f/128.f);
            float rs = rsqrtf(q*(1.f/128.f) - mu*mu + EPS_);
            float o[8];
            #pragma unroll
            for (int j = 0; j < 4; j++) {
                o[2*j]   = (rc[i][j].x - mu)*rs*gv[j].x + bev[j].x;
                o[2*j+1] = (rc[i][j].y - mu)*rs*gv[j].y + bev[j].y;
            }
            float* op = zout + (size_t)(row0 + r0 + i)*D_ + c0;
            *(float4*)op     = make_float4(o[0],o[1],o[2],o[3]);
            *(float4*)(op+4) = make_float4(o[4],o[5],o[6],o[7]);
        }
    }
}

// ============ K4: EMA recurrence + SiLU + transpose (unchanged) ============
__global__ void k4_ema(const float* __restrict__ omega)
{
    __shared__ float tile[128*65];
    int bn = blockIdx.x, d = threadIdx.x;
    float q0 = g_ema[d*4+0], a0 = g_ema[d*4+1];
    float q1 = g_ema[d*4+2], a1 = g_ema[d*4+3];
    float om = omega[d];
    const float* src = g_bufA + (size_t)bn*PNUM_*D_ + d;
    float* dst = g_u + (size_t)bn*KHEAD_;
    float s0 = 0.f, s1 = 0.f;
    for (int chunk = 0; chunk < 4; chunk++) {
        int tbase = chunk*64;
        int tn = (PNUM_ - tbase < 64) ? (PNUM_ - tbase) : 64;
        #pragma unroll 4
        for (int i = 0; i < tn; i++) {
            float xv = src[(size_t)(tbase + i)*D_];
            s0 = fmaf(s0, q0, xv);
            s1 = fmaf(s1, q1, xv);
            float v = fmaf(om, xv, fmaf(a0, s0, a1*s1));
            tile[d*65 + i] = v * (1.f/(1.f + __expf(-v)));
        }
        __syncthreads();
        for (int i = d; i < 128*64; i += 128) {
            int dd = i >> 6, tt = i & 63;
            if (tt < tn) dst[dd*PNUM_ + tbase + tt] = tile[dd*65 + tt];
        }
        __syncthreads();
    }
}

// ============ K5: head GEMM [1344 x 32640] @ [32640 x 96] ============
__global__ void k5_init(const float* __restrict__ hb, float* __restrict__ out)
{
    int i = blockIdx.x*blockDim.x + threadIdx.x;
    if (i < BN_*PRED_) out[i] = hb[i % PRED_];
}

__global__ __launch_bounds__(192, 1)
void k5_head(const float* __restrict__ hw, float* __restrict__ out)
{
    __shared__ float u2[64*64];                // [k][r ^ SWR(k)]
    __shared__ float2 ws2[64*48];              // slot j*24+cg <-> cp=cg*2+j
    int tid = threadIdx.x;
    int cg = tid % 24, rg = tid / 24;          // 24 x 8
    int c0 = cg*4, r0 = rg*8;
    int row0 = blockIdx.x * 64;
    int k0base = blockIdx.y * 3264;            // 10 splits x 51 chunks x 64

    float2 acc[8][2];
    #pragma unroll
    for (int i = 0; i < 8; i++) { acc[i][0] = make_float2(0.f,0.f); acc[i][1] = make_float2(0.f,0.f); }

    for (int ch = 0; ch < 51; ch++) {
        int k0 = k0base + ch*64;
        __syncthreads();
        for (int idx = tid; idx < 64*16; idx += 192) {
            int r = idx >> 4, q = (idx & 15)*4;
            float4 v = *(const float4*)(g_u + (size_t)(row0 + r)*KHEAD_ + k0 + q);
            int rr = r ^ SWR(q);
            u2[(q+0)*64 + rr] = v.x;
            u2[(q+1)*64 + rr] = v.y;
            u2[(q+2)*64 + rr] = v.z;
            u2[(q+3)*64 + rr] = v.w;
        }
        for (int idx = tid; idx < 64*48; idx += 192) {
            int k = idx / 48, s = idx - k*48;
            int cp = (s % 24)*2 + s/24;
            ws2[idx] = *(const float2*)(hw + (size_t)(k0 + k)*96 + 2*cp);
        }
        __syncthreads();
        #pragma unroll 2
        for (int kk = 0; kk < 64; kk++) {
            int rx = r0 ^ SWR(kk);
            float4 xa = *(const float4*)(u2 + kk*64 + rx);
            float4 xb = *(const float4*)(u2 + kk*64 + rx + 4);
            float2 w0 = ws2[kk*48 + cg];
            float2 w1v = ws2[kk*48 + 24 + cg];
            float2 xd[8] = {dup2(xa.x),dup2(xa.y),dup2(xa.z),dup2(xa.w),
                            dup2(xb.x),dup2(xb.y),dup2(xb.z),dup2(xb.w)};
            #pragma unroll
            for (int i = 0; i < 8; i++) {
                acc[i][0] = ffma2(xd[i], w0,  acc[i][0]);
                acc[i][1] = ffma2(xd[i], w1v, acc[i][1]);
            }
        }
    }
    #pragma unroll
    for (int i = 0; i < 8; i++) {
        float* op = out + (size_t)(row0 + r0 + i)*PRED_ + c0;
        atomicAdd(op+0, acc[i][0].x);
        atomicAdd(op+1, acc[i][0].y);
        atomicAdd(op+2, acc[i][1].x);
        atomicAdd(op+3, acc[i][1].y);
    }
}

// ============ launch ============
extern "C" void kernel_launch(void* const* d_in, const int* in_sizes, int n_in,
                              void* d_out, int out_size)
{
    const float* x       = (const float*)d_in[0];
    const float* fp_w1   = (const float*)d_in[1];
    const float* fp_b1   = (const float*)d_in[2];
    const float* fp_w2   = (const float*)d_in[3];
    const float* fp_b2   = (const float*)d_in[4];
    const float* fp_wr   = (const float*)d_in[5];
    const float* fp_br   = (const float*)d_in[6];
    const float* fp_g    = (const float*)d_in[7];
    const float* fp_be   = (const float*)d_in[8];
    const float* enc_w1  = (const float*)d_in[9];
    const float* enc_b1  = (const float*)d_in[10];
    const float* enc_w2  = (const float*)d_in[11];
    const float* enc_b2  = (const float*)d_in[12];
    const float* enc_wr  = (const float*)d_in[13];
    const float* enc_br  = (const float*)d_in[14];
    const float* enc_g   = (const float*)d_in[15];
    const float* enc_be  = (const float*)d_in[16];
    const float* e_delta = (const float*)d_in[17];
    const float* e_alpha = (const float*)d_in[18];
    const float* e_beta  = (const float*)d_in[19];
    const float* e_gamma = (const float*)d_in[20];
    const float* e_omega = (const float*)d_in[21];
    const float* head_w  = (const float*)d_in[22];
    const float* head_b  = (const float*)d_in[23];
    float* out = (float*)d_out;

    cudaFuncSetAttribute(k1_featproj, cudaFuncAttributeMaxDynamicSharedMemorySize, SM1_BYTES);
    cudaFuncSetAttribute(k2_encoder,  cudaFuncAttributeMaxDynamicSharedMemorySize, SM2_BYTES);

    k0_emaparam<<<1, 128>>>(e_delta, e_alpha, e_beta, e_gamma);
    k1_featproj<<<148, 256, SM1_BYTES>>>(x, fp_w1, fp_b1, fp_w2, fp_b2, fp_wr, fp_br, fp_g, fp_be);
    k2_encoder<<<148, 256, SM2_BYTES>>>(enc_w1, enc_b1, enc_w2, enc_b2, enc_wr, enc_br, enc_g, enc_be, 0);
    k2_encoder<<<148, 256, SM2_BYTES>>>(enc_w1, enc_b1, enc_w2, enc_b2, enc_wr, enc_br, enc_g, enc_be, 1);
    k4_ema<<<BN_, 128>>>(e_omega);
    k5_init<<<(BN_*PRED_ + 255)/256, 256>>>(head_b, out);
    k5_head<<<dim3(21, 10), 192>>>(head_w, out);
}